// round 2
// baseline (speedup 1.0000x reference)
#include <cuda_runtime.h>
#include <cstdint>
#include <cmath>

typedef unsigned long long ull;

#define DM 768
#define NQ 256
#define NM 512

#define FMA2(acc, a, b) asm("fma.rn.f32x2 %0, %1, %2, %0;" : "+l"(acc) : "l"(a), "l"(b))
#define DUP2(d, s)      asm("mov.b64 %0, {%1, %1};" : "=l"(d) : "f"(s))
#define UNPK2(lo, hi, s) asm("mov.b64 {%0, %1}, %2;" : "=f"(lo), "=f"(hi) : "l"(s))

// ---------------- scratch (__device__ globals; no allocation allowed) -------
__device__ float g_q  [NQ*DM];
__device__ float g_ip [NM*DM];
__device__ float g_tp [NM*DM];
__device__ float g_qh [NQ*DM];
__device__ float g_kd [NM*DM];
__device__ float g_vd [NM*DM];
__device__ float g_vt [NM*DM];
__device__ float g_W01[DM*256];
__device__ float g_b01[256];
__device__ float g_Ah [NM*8*256];   // [m][h][256]  (from vd = v_img - v_tgt)
__device__ float g_At [NM*8*256];   // [m][h][256]  (from vt)
__device__ float g_Bm [NM*256];     // [m][256]
__device__ float g_w  [NQ*NM*8];    // [n][m][h]

// ---------------- generic multi-GEMM: C = scale*( (A - A2?) @ W + bias ) ----
// 64x64 tile, 64 threads, 8x8 microtile, packed f32x2 accumulation.
struct GDesc {
    const float* A;
    const float* A2;     // optional: compute (A - A2)
    const float* W;      // K x N row-major (ldw)
    const float* bias;   // optional, length N
    float*       C;
    int M, N, K, lda, ldw, ldc;
    float scale;
};
struct GParams { GDesc d[16]; };

__global__ __launch_bounds__(64) void sgemm2(GParams p) {
    GDesc d = p.d[blockIdx.z];
    const int m0 = blockIdx.y * 64, n0 = blockIdx.x * 64;
    if (m0 >= d.M || n0 >= d.N) return;

    __shared__ __align__(16) float As[2][16][64];   // [k][m]
    __shared__ __align__(16) float Bs[2][16][64];   // [k][n]

    const int t = threadIdx.x;
    const int KT = d.K >> 4;

    const float* Ap  = d.A + (size_t)(m0 + t) * d.lda;
    const float* A2p = d.A2 ? d.A2 + (size_t)(m0 + t) * d.lda : nullptr;
    const float* Wp  = d.W + (size_t)(t >> 2) * d.ldw + n0 + (t & 3) * 16;

    float4 aR[4], bR[4];

    // ---- load tile 0 ----
#pragma unroll
    for (int i = 0; i < 4; i++) {
        aR[i] = *(const float4*)(Ap + i * 4);
        bR[i] = *(const float4*)(Wp + i * 4);
    }
    if (A2p) {
#pragma unroll
        for (int i = 0; i < 4; i++) {
            float4 a2 = *(const float4*)(A2p + i * 4);
            aR[i].x -= a2.x; aR[i].y -= a2.y; aR[i].z -= a2.z; aR[i].w -= a2.w;
        }
    }
#pragma unroll
    for (int i = 0; i < 4; i++) {
        As[0][i*4+0][t] = aR[i].x;
        As[0][i*4+1][t] = aR[i].y;
        As[0][i*4+2][t] = aR[i].z;
        As[0][i*4+3][t] = aR[i].w;
        *(float4*)&Bs[0][t >> 2][(t & 3) * 16 + i * 4] = bR[i];
    }
    __syncthreads();

    ull acc[32];
#pragma unroll
    for (int i = 0; i < 32; i++) acc[i] = 0ULL;

    const int aoff = (t & 7) * 8;
    const int boff = (t >> 3) * 8;

    for (int kt = 0; kt < KT; kt++) {
        const int cur = kt & 1;
        const bool more = (kt + 1 < KT);
        if (more) {
            const int kb = (kt + 1) * 16;
#pragma unroll
            for (int i = 0; i < 4; i++) {
                aR[i] = *(const float4*)(Ap + kb + i * 4);
                bR[i] = *(const float4*)(Wp + (size_t)kb * d.ldw + i * 4);
            }
            if (A2p) {
#pragma unroll
                for (int i = 0; i < 4; i++) {
                    float4 a2 = *(const float4*)(A2p + kb + i * 4);
                    aR[i].x -= a2.x; aR[i].y -= a2.y; aR[i].z -= a2.z; aR[i].w -= a2.w;
                }
            }
        }
#pragma unroll
        for (int k = 0; k < 16; k++) {
            ulonglong2 a01 = *(const ulonglong2*)&As[cur][k][aoff];
            ulonglong2 a23 = *(const ulonglong2*)&As[cur][k][aoff + 4];
            float4 b0 = *(const float4*)&Bs[cur][k][boff];
            float4 b1 = *(const float4*)&Bs[cur][k][boff + 4];
            ull ap[4] = {a01.x, a01.y, a23.x, a23.y};
            ull bd[8];
            DUP2(bd[0], b0.x); DUP2(bd[1], b0.y); DUP2(bd[2], b0.z); DUP2(bd[3], b0.w);
            DUP2(bd[4], b1.x); DUP2(bd[5], b1.y); DUP2(bd[6], b1.z); DUP2(bd[7], b1.w);
#pragma unroll
            for (int ip = 0; ip < 4; ip++)
#pragma unroll
                for (int j = 0; j < 8; j++)
                    FMA2(acc[ip * 8 + j], ap[ip], bd[j]);
        }
        if (more) {
            const int nxt = cur ^ 1;
#pragma unroll
            for (int i = 0; i < 4; i++) {
                As[nxt][i*4+0][t] = aR[i].x;
                As[nxt][i*4+1][t] = aR[i].y;
                As[nxt][i*4+2][t] = aR[i].z;
                As[nxt][i*4+3][t] = aR[i].w;
                *(float4*)&Bs[nxt][t >> 2][(t & 3) * 16 + i * 4] = bR[i];
            }
            __syncthreads();
        }
    }

    // ---- epilogue ----
    float bias[8];
    if (d.bias) {
        float4 x = *(const float4*)(d.bias + n0 + boff);
        float4 y = *(const float4*)(d.bias + n0 + boff + 4);
        bias[0]=x.x; bias[1]=x.y; bias[2]=x.z; bias[3]=x.w;
        bias[4]=y.x; bias[5]=y.y; bias[6]=y.z; bias[7]=y.w;
    } else {
#pragma unroll
        for (int j = 0; j < 8; j++) bias[j] = 0.f;
    }
    const int mr = m0 + aoff, nc = n0 + boff;
#pragma unroll
    for (int ip = 0; ip < 4; ip++) {
        float lo[8], hi[8];
#pragma unroll
        for (int j = 0; j < 8; j++) UNPK2(lo[j], hi[j], acc[ip * 8 + j]);
        float* r0 = d.C + (size_t)(mr + ip * 2) * d.ldc + nc;
        float* r1 = r0 + d.ldc;
        float4 o;
        o.x = d.scale*(lo[0]+bias[0]); o.y = d.scale*(lo[1]+bias[1]);
        o.z = d.scale*(lo[2]+bias[2]); o.w = d.scale*(lo[3]+bias[3]);
        *(float4*)r0 = o;
        o.x = d.scale*(lo[4]+bias[4]); o.y = d.scale*(lo[5]+bias[5]);
        o.z = d.scale*(lo[6]+bias[6]); o.w = d.scale*(lo[7]+bias[7]);
        *(float4*)(r0 + 4) = o;
        o.x = d.scale*(hi[0]+bias[0]); o.y = d.scale*(hi[1]+bias[1]);
        o.z = d.scale*(hi[2]+bias[2]); o.w = d.scale*(hi[3]+bias[3]);
        *(float4*)r1 = o;
        o.x = d.scale*(hi[4]+bias[4]); o.y = d.scale*(hi[5]+bias[5]);
        o.z = d.scale*(hi[6]+bias[6]); o.w = d.scale*(hi[7]+bias[7]);
        *(float4*)(r1 + 4) = o;
    }
}

// ---------------- b01 = bo @ W1 + b1 (256 outputs) -------------------------
__global__ void b01_kernel(const float* __restrict__ bo, const float* __restrict__ W1,
                           const float* __restrict__ b1, float* __restrict__ b01) {
    int j = threadIdx.x;   // 256
    float s = b1[j];
#pragma unroll 8
    for (int k = 0; k < DM; k++)
        s = fmaf(bo[k], W1[(size_t)k*256 + j], s);
    b01[j] = s;
}

// ---------------- Bm[m][j] = b01[j] + sum_h At[m][h][j] --------------------
__global__ void reduce_kernel(const float* __restrict__ At, const float* __restrict__ b01,
                              float* __restrict__ Bm) {
    int m = blockIdx.x, j = threadIdx.x;
    float s = b01[j];
#pragma unroll
    for (int h = 0; h < 8; h++)
        s += At[(size_t)m*2048 + h*256 + j];
    Bm[(size_t)m*256 + j] = s;
}

// ---------------- logits: w[n,m,h] = sigmoid( qh[n,h,:] . kd[m,h,:] ) ------
__global__ __launch_bounds__(256) void logits_kernel(const float* __restrict__ qh,
                                                     const float* __restrict__ kd,
                                                     float* __restrict__ wbuf) {
    const int h  = blockIdx.z;
    const int m0 = blockIdx.x * 64, n0 = blockIdx.y * 64;
    __shared__ __align__(16) float Qs[16][68];
    __shared__ __align__(16) float Ks[16][68];

    const int tid = threadIdx.x;
    const int tx = tid & 15, ty = tid >> 4;
    const int lrow = tid >> 2, lc4 = tid & 3;

    const float* qp = qh + (size_t)(n0 + lrow)*DM + h*96 + lc4*4;
    const float* kp = kd + (size_t)(m0 + lrow)*DM + h*96 + lc4*4;

    float acc[4][4];
#pragma unroll
    for (int i = 0; i < 4; i++)
#pragma unroll
        for (int j = 0; j < 4; j++) acc[i][j] = 0.f;

    for (int k0 = 0; k0 < 96; k0 += 16) {
        float4 qv = *(const float4*)(qp + k0);
        float4 kv = *(const float4*)(kp + k0);
        __syncthreads();
        Qs[lc4*4+0][lrow] = qv.x;
        Qs[lc4*4+1][lrow] = qv.y;
        Qs[lc4*4+2][lrow] = qv.z;
        Qs[lc4*4+3][lrow] = qv.w;
        Ks[lc4*4+0][lrow] = kv.x;
        Ks[lc4*4+1][lrow] = kv.y;
        Ks[lc4*4+2][lrow] = kv.z;
        Ks[lc4*4+3][lrow] = kv.w;
        __syncthreads();
#pragma unroll
        for (int k = 0; k < 16; k++) {
            float4 a = *(const float4*)&Qs[k][ty*4];
            float4 b = *(const float4*)&Ks[k][tx*4];
            float ar[4] = {a.x, a.y, a.z, a.w};
            float br[4] = {b.x, b.y, b.z, b.w};
#pragma unroll
            for (int i = 0; i < 4; i++)
#pragma unroll
                for (int j = 0; j < 4; j++)
                    acc[i][j] = fmaf(ar[i], br[j], acc[i][j]);
        }
    }
#pragma unroll
    for (int i = 0; i < 4; i++)
#pragma unroll
        for (int j = 0; j < 4; j++) {
            int n = n0 + ty*4 + i, m = m0 + tx*4 + j;
            float wv = 1.f / (1.f + expf(-acc[i][j]));
            wbuf[((size_t)n*NM + m)*8 + h] = wv;
        }
}

// ---------------- fused tail: h=relu(B+Σw·A); h2=relu(h@W2+b2); tanh -------
__global__ __launch_bounds__(256, 2) void fuse_kernel(
    const float* __restrict__ Abuf, const float* __restrict__ Bbuf,
    const float* __restrict__ wbuf, const float* __restrict__ W2,
    const float* __restrict__ b2, const float* __restrict__ W3,
    const float* __restrict__ b3, float* __restrict__ out) {

    __shared__ __align__(16) float A_s[8*256];
    __shared__ __align__(16) float B_s[256];
    __shared__ __align__(16) float w2s[64*64];   // chunk of 64 j-rows of W2
    __shared__ float b2s[64], W3s[64];
    __shared__ float b3s;

    const int m = blockIdx.x, tid = threadIdx.x;

    // stage A[m] (8x256) and B[m] (256)
    {
        const float4* Ag = (const float4*)(Abuf + (size_t)m*2048);
        float4* A4 = (float4*)A_s;
        A4[tid]       = Ag[tid];
        A4[tid + 256] = Ag[tid + 256];
        B_s[tid] = Bbuf[(size_t)m*256 + tid];
        if (tid < 64) { b2s[tid] = b2[tid]; W3s[tid] = W3[tid]; }
        if (tid == 0) b3s = b3[0];
    }

    const int n = tid;
    const float4* wp = (const float4*)(wbuf + ((size_t)n*NM + m)*8);
    float4 wA = wp[0], wB = wp[1];
    float wr[8] = {wA.x, wA.y, wA.z, wA.w, wB.x, wB.y, wB.z, wB.w};

    ull acc[32];
#pragma unroll
    for (int t = 0; t < 32; t++) acc[t] = 0ULL;

    for (int c = 0; c < 4; c++) {
        __syncthreads();
        {
            const float4* w2g = (const float4*)(W2 + c*4096);
            float4* w2s4 = (float4*)w2s;
#pragma unroll
            for (int r = 0; r < 4; r++) w2s4[tid + r*256] = w2g[tid + r*256];
        }
        __syncthreads();

        for (int jj = 0; jj < 64; jj += 4) {
            const int j = c*64 + jj;
            float4 hb = *(const float4*)&B_s[j];
            float hv[4] = {hb.x, hb.y, hb.z, hb.w};
#pragma unroll
            for (int h = 0; h < 8; h++) {
                float4 a = *(const float4*)&A_s[h*256 + j];
                hv[0] = fmaf(wr[h], a.x, hv[0]);
                hv[1] = fmaf(wr[h], a.y, hv[1]);
                hv[2] = fmaf(wr[h], a.z, hv[2]);
                hv[3] = fmaf(wr[h], a.w, hv[3]);
            }
#pragma unroll
            for (int u = 0; u < 4; u++) {
                float hj = fmaxf(hv[u], 0.f);
                ull hh;
                asm("mov.b64 %0, {%1, %1};" : "=l"(hh) : "f"(hj));
                const ulonglong2* row = (const ulonglong2*)(w2s + (jj + u)*64);
#pragma unroll
                for (int t = 0; t < 16; t++) {
                    ulonglong2 pv = row[t];
                    asm("fma.rn.f32x2 %0, %1, %2, %0;" : "+l"(acc[2*t+0]) : "l"(hh), "l"(pv.x));
                    asm("fma.rn.f32x2 %0, %1, %2, %0;" : "+l"(acc[2*t+1]) : "l"(hh), "l"(pv.y));
                }
            }
        }
    }

    float s = b3s;
#pragma unroll
    for (int t = 0; t < 32; t++) {
        float lo, hi;
        UNPK2(lo, hi, acc[t]);
        lo = fmaxf(lo + b2s[2*t+0], 0.f);
        hi = fmaxf(hi + b2s[2*t+1], 0.f);
        s = fmaf(lo, W3s[2*t+0], s);
        s = fmaf(hi, W3s[2*t+1], s);
    }
    out[(size_t)n*NM + m] = 0.5f * tanhf(s);
}

// ---------------- launch ----------------------------------------------------
extern "C" void kernel_launch(void* const* d_in, const int* in_sizes, int n_in,
                              void* d_out, int out_size) {
    const float* Q   = (const float*)d_in[0];
    const float* IMG = (const float*)d_in[1];
    const float* TGT = (const float*)d_in[2];
    const float* Wq  = (const float*)d_in[3];
    const float* bq  = (const float*)d_in[4];
    const float* Wi  = (const float*)d_in[5];
    const float* bi  = (const float*)d_in[6];
    const float* Wt  = (const float*)d_in[7];
    const float* bt  = (const float*)d_in[8];
    const float* Wiq = (const float*)d_in[9];
    const float* biq = (const float*)d_in[10];
    const float* Wik = (const float*)d_in[11];
    const float* bik = (const float*)d_in[12]; (void)bik; // cancels in k-diff
    const float* Wiv = (const float*)d_in[13];
    const float* biv = (const float*)d_in[14]; (void)biv; // cancels: handled via At path
    const float* Wo  = (const float*)d_in[15];
    const float* bo  = (const float*)d_in[16];
    const float* W1  = (const float*)d_in[17];
    const float* b1  = (const float*)d_in[18];
    const float* W2  = (const float*)d_in[19];
    const float* b2  = (const float*)d_in[20];
    const float* W3  = (const float*)d_in[21];
    const float* b3  = (const float*)d_in[22];
    float* out = (float*)d_out;

    float *q, *ip, *tp, *qh, *kd, *vd, *vt, *W01, *b01, *Ah, *At, *Bm, *wb;
    cudaGetSymbolAddress((void**)&q,   g_q);
    cudaGetSymbolAddress((void**)&ip,  g_ip);
    cudaGetSymbolAddress((void**)&tp,  g_tp);
    cudaGetSymbolAddress((void**)&qh,  g_qh);
    cudaGetSymbolAddress((void**)&kd,  g_kd);
    cudaGetSymbolAddress((void**)&vd,  g_vd);
    cudaGetSymbolAddress((void**)&vt,  g_vt);
    cudaGetSymbolAddress((void**)&W01, g_W01);
    cudaGetSymbolAddress((void**)&b01, g_b01);
    cudaGetSymbolAddress((void**)&Ah,  g_Ah);
    cudaGetSymbolAddress((void**)&At,  g_At);
    cudaGetSymbolAddress((void**)&Bm,  g_Bm);
    cudaGetSymbolAddress((void**)&wb,  g_w);

    const float scale = 1.0f / sqrtf(96.0f);

    // NOTE on biv: attn value term = w*v_img + (1-w)*v_tgt. Writing it as
    // v_tgt + w*(v_img - v_tgt), the biv bias cancels in the diff (vd) and is
    // carried entirely by the vt path (which keeps biv).

    // L1: stage-1 projections + W01 fold (all independent)
    GParams p1 = {};
    p1.d[0] = {Q,   0, Wq, bq, q,   256, 768, 768, 768, 768, 768, 1.f};
    p1.d[1] = {IMG, 0, Wi, bi, ip,  512, 768, 768, 768, 768, 768, 1.f};
    p1.d[2] = {TGT, 0, Wt, bt, tp,  512, 768, 768, 768, 768, 768, 1.f};
    p1.d[3] = {Wo,  0, W1, 0,  W01, 768, 256, 768, 768, 256, 256, 1.f};
    sgemm2<<<dim3(12, 12, 4), 64>>>(p1);

    b01_kernel<<<1, 256>>>(bo, W1, b1, b01);

    // L2: stage-2 projections (k/v bias cancels in diffs)
    GParams p2 = {};
    p2.d[0] = {q,  0,  Wiq, biq, qh, 256, 768, 768, 768, 768, 768, scale};
    p2.d[1] = {ip, tp, Wik, 0,   kd, 512, 768, 768, 768, 768, 768, 1.f};
    p2.d[2] = {ip, tp, Wiv, 0,   vd, 512, 768, 768, 768, 768, 768, 1.f};
    p2.d[3] = {tp, 0,  Wiv, 0,   vt, 512, 768, 768, 768, 768, 768, 1.f};
    sgemm2<<<dim3(12, 8, 4), 64>>>(p2);

    // L3: per-head A[m,h,:] = vd_h @ W01_h  and  At[m,h,:] = vt_h @ W01_h
    // (Bm = sum_h At + b01 is computed by reduce_kernel; avoids a K=768 GEMM)
    // biv contribution to Bm: biv@Wiv... NOTE biv enters v_tgt = tp@Wiv + biv.
    // We dropped biv from vt above, so add it back via b01':
    //   Bm = (vt_nobias + biv)@W01 + b01 = sum_h At + (biv@W01 + b01)
    // b01_kernel computes bo@W1 + b1; we need + biv@W01 = biv@(Wo@W1).
    // Equivalent: (biv@Wo)@W1. Fold into b01 via a second pass below.
    GParams p3 = {};
    for (int h = 0; h < 8; h++) {
        p3.d[h]   = {vd + h*96, 0, W01 + h*96*256, 0, Ah + h*256,
                     512, 256, 96, 768, 256, 2048, 1.f};
        p3.d[8+h] = {vt + h*96, 0, W01 + h*96*256, 0, At + h*256,
                     512, 256, 96, 768, 256, 2048, 1.f};
    }
    sgemm2<<<dim3(4, 8, 16), 64>>>(p3);

    // b01 += biv @ W01  (tiny: 256 threads x 768 fma) — fold biv here
    // Implemented by reusing b01_kernel pattern inline via a lambda-less kernel:
    // (separate kernel below)
    extern __global__ void b01_add_kernel(const float*, const float*, float*);
    b01_add_kernel<<<1, 256>>>(biv, W01, b01);

    // reduce: Bm = b01 + sum_h At
    reduce_kernel<<<NM, 256>>>(At, b01, Bm);

    // L4: attention weights (sigmoid of logit diff)
    logits_kernel<<<dim3(8, 4, 8), 256>>>(qh, kd, wb);

    // L5: fused weighted-combine + MLP tail
    fuse_kernel<<<NM, 256>>>(Ah, Bm, wb, W2, b2, W3, b3, out);
}

// b01 += biv @ W01
__global__ void b01_add_kernel(const float* __restrict__ biv,
                               const float* __restrict__ W01,
                               float* __restrict__ b01) {
    int j = threadIdx.x;   // 256
    float s = 0.f;
#pragma unroll 8
    for (int k = 0; k < DM; k++)
        s = fmaf(biv[k], W01[(size_t)k*256 + j], s);
    b01[j] += s;
}